// round 1
// baseline (speedup 1.0000x reference)
#include <cuda_runtime.h>
#include <math.h>

#define BB 64
#define LL 1024
#define DD 512
#define HH 1024
#define GG 4096          // 4*HH
#define NCTA 128         // phase-2 persistent CTAs (<= 148 SMs, all co-resident)

// ---------------- scratch (static device allocations only) ----------------
static __device__ float    g_gx[(size_t)LL * BB * GG];   // [t][b][4H]  (1 GiB)
static __device__ float    g_hbuf[2][BB * HH];
static __device__ float    g_cbuf[BB * HH];
static __device__ unsigned g_bar[LL];                    // one counter per step
static __device__ int      g_mask_mode;                  // 0=byte 1=int32 2=float32

// ---------------- init: zero state + barrier counters, probe mask dtype ----
__global__ void init_kernel(const void* mask)
{
    int i = blockIdx.x * blockDim.x + threadIdx.x;
    if (i < BB * HH) { g_hbuf[0][i] = 0.0f; g_cbuf[i] = 0.0f; }
    if (i < LL)      { g_bar[i] = 0u; }
    if (i == 0) {
        // lengths >= L/2 = 512, so mask[0, 0..3] are all True.
        int v = *(const int*)mask;
        if (v == 1)                 g_mask_mode = 1;   // int32 0/1
        else if (v == 0x3F800000)   g_mask_mode = 2;   // float32 0/1
        else                        g_mask_mode = 0;   // 1-byte bool
    }
}

// ---------------- phase 1: g_gx[t][b][n] = X @ W_ih^T + b_ih + b_hh --------
// C[m,n] = sum_k X[m,k] * Wih[n,k],  m = b*L + t.  Stored transposed to [t][b][n].
__global__ __launch_bounds__(256)
void gemm_x_kernel(const float* __restrict__ X, const float* __restrict__ W,
                   const float* __restrict__ bih, const float* __restrict__ bhh)
{
    __shared__ __align__(16) float As[2][16][128];
    __shared__ __align__(16) float Bs[2][16][128];

    const int tid = threadIdx.x;
    const int tx  = tid & 15;        // 0..15 (col groups of 8)
    const int ty  = tid >> 4;        // 0..15 (row groups of 8)
    const int m0  = blockIdx.y * 128;
    const int n0  = blockIdx.x * 128;

    float acc[8][8];
#pragma unroll
    for (int i = 0; i < 8; i++)
#pragma unroll
        for (int j = 0; j < 8; j++) acc[i][j] = 0.0f;

    const int ia0 = tid;             // float4 slot 0..255
    const int ia1 = tid + 256;       // float4 slot 256..511
    const int r0a = ia0 >> 2, kc0 = (ia0 & 3) << 2;
    const int r1a = ia1 >> 2, kc1 = (ia1 & 3) << 2;

    float4 ra0, ra1, rb0, rb1;
    ra0 = *(const float4*)(X + (size_t)(m0 + r0a) * DD + kc0);
    ra1 = *(const float4*)(X + (size_t)(m0 + r1a) * DD + kc1);
    rb0 = *(const float4*)(W + (size_t)(n0 + r0a) * DD + kc0);
    rb1 = *(const float4*)(W + (size_t)(n0 + r1a) * DD + kc1);

    int buf = 0;
    for (int kt = 0; kt < DD; kt += 16) {
        As[buf][kc0 + 0][r0a] = ra0.x; As[buf][kc0 + 1][r0a] = ra0.y;
        As[buf][kc0 + 2][r0a] = ra0.z; As[buf][kc0 + 3][r0a] = ra0.w;
        As[buf][kc1 + 0][r1a] = ra1.x; As[buf][kc1 + 1][r1a] = ra1.y;
        As[buf][kc1 + 2][r1a] = ra1.z; As[buf][kc1 + 3][r1a] = ra1.w;
        Bs[buf][kc0 + 0][r0a] = rb0.x; Bs[buf][kc0 + 1][r0a] = rb0.y;
        Bs[buf][kc0 + 2][r0a] = rb0.z; Bs[buf][kc0 + 3][r0a] = rb0.w;
        Bs[buf][kc1 + 0][r1a] = rb1.x; Bs[buf][kc1 + 1][r1a] = rb1.y;
        Bs[buf][kc1 + 2][r1a] = rb1.z; Bs[buf][kc1 + 3][r1a] = rb1.w;
        __syncthreads();

        if (kt + 16 < DD) {
            ra0 = *(const float4*)(X + (size_t)(m0 + r0a) * DD + kt + 16 + kc0);
            ra1 = *(const float4*)(X + (size_t)(m0 + r1a) * DD + kt + 16 + kc1);
            rb0 = *(const float4*)(W + (size_t)(n0 + r0a) * DD + kt + 16 + kc0);
            rb1 = *(const float4*)(W + (size_t)(n0 + r1a) * DD + kt + 16 + kc1);
        }

#pragma unroll
        for (int kk = 0; kk < 16; kk++) {
            float a0[8], b0[8];
            *(float4*)(&a0[0]) = *(const float4*)(&As[buf][kk][ty * 8]);
            *(float4*)(&a0[4]) = *(const float4*)(&As[buf][kk][ty * 8 + 4]);
            *(float4*)(&b0[0]) = *(const float4*)(&Bs[buf][kk][tx * 8]);
            *(float4*)(&b0[4]) = *(const float4*)(&Bs[buf][kk][tx * 8 + 4]);
#pragma unroll
            for (int i = 0; i < 8; i++)
#pragma unroll
                for (int j = 0; j < 8; j++) acc[i][j] += a0[i] * b0[j];
        }
        buf ^= 1;
    }

    float bias[8];
#pragma unroll
    for (int j = 0; j < 8; j++) {
        int n = n0 + tx * 8 + j;
        bias[j] = bih[n] + bhh[n];
    }
#pragma unroll
    for (int rr = 0; rr < 8; rr++) {
        int m = m0 + ty * 8 + rr;
        int b = m >> 10;        // /L
        int t = m & 1023;       // %L
        float* dst = g_gx + ((size_t)t * BB + b) * GG + n0 + tx * 8;
        float4 v0, v1;
        v0.x = acc[rr][0] + bias[0]; v0.y = acc[rr][1] + bias[1];
        v0.z = acc[rr][2] + bias[2]; v0.w = acc[rr][3] + bias[3];
        v1.x = acc[rr][4] + bias[4]; v1.y = acc[rr][5] + bias[5];
        v1.z = acc[rr][6] + bias[6]; v1.w = acc[rr][7] + bias[7];
        *(float4*)(dst)     = v0;
        *(float4*)(dst + 4) = v1;
    }
}

// ---------------- phase 2: persistent sequential LSTM steps ----------------
// CTA j owns h-columns [j*8, j*8+8). Per step it computes the 64x32 gate slab
// (4 gates x 8 h-cols) = Hold(64x1024) @ Whh_slice^T, then the elementwise
// cell update for its columns. h is double-buffered; c is CTA-private.
__device__ __forceinline__ float sigmoidf_(float x) {
    return 1.0f / (1.0f + expf(-x));
}

__global__ __launch_bounds__(128)
void lstm_kernel(const float* __restrict__ Whh,
                 const unsigned char* __restrict__ m8,
                 const int* __restrict__ m32,
                 const float* __restrict__ mf,
                 const float* __restrict__ wci,
                 const float* __restrict__ wcf,
                 const float* __restrict__ wco,
                 float* __restrict__ out)
{
    __shared__ __align__(16) float As[2][16][64];
    __shared__ __align__(16) float Bs[2][16][32];
    __shared__ __align__(16) float Gs[64][33];
    __shared__ float s_wci[8], s_wcf[8], s_wco[8];

    const int tid = threadIdx.x;
    const int tx  = tid & 7;         // 0..7  (col groups of 4)
    const int ty  = tid >> 3;        // 0..15 (row groups of 4)
    const int cta = blockIdx.x;
    const int h0  = cta * 8;
    const int r0  = ty * 4;
    const int c0  = tx * 4;

    if (tid < 8) {
        s_wci[tid] = wci[h0 + tid];
        s_wcf[tid] = wcf[h0 + tid];
        s_wco[tid] = wco[h0 + tid];
    }
    __syncthreads();
    const int mmode = g_mask_mode;

    // B-tile loader mapping: thread -> (cc, kc) of the 32x16 W tile
    const int bcc = tid >> 2;                      // 0..31 gate-col within CTA
    const int bkc = (tid & 3) << 2;                // 0,4,8,12
    const int brow = (bcc >> 3) * HH + h0 + (bcc & 7);   // W_hh row (gate col)
    const float* wptr = Whh + (size_t)brow * HH + bkc;

    // A-tile loader mapping: two float4 slots per thread over 64x16
    const int ia0 = tid, ia1 = tid + 128;
    const int ar0 = ia0 >> 2, akc0 = (ia0 & 3) << 2;
    const int ar1 = ia1 >> 2, akc1 = (ia1 & 3) << 2;

    // acc column -> global gate column base (4 consecutive cols in one gate)
    const int ggate = c0 >> 3;
    const int nacc  = ggate * HH + h0 + (c0 & 7);

    for (int t = 0; t < LL; ++t) {
        const float* hb = g_hbuf[t & 1];
        float*       hn = g_hbuf[(t + 1) & 1];
        const float* gx = g_gx + (size_t)t * (BB * GG);

        // init accumulators from precomputed x-projection (+ biases)
        float acc[4][4];
#pragma unroll
        for (int rr = 0; rr < 4; rr++) {
            float4 v = *(const float4*)(gx + (size_t)(r0 + rr) * GG + nacc);
            acc[rr][0] = v.x; acc[rr][1] = v.y; acc[rr][2] = v.z; acc[rr][3] = v.w;
        }

        // prefetch k-tile 0 (h via L2-coherent loads; Whh via normal loads)
        float4 ra0 = __ldcg((const float4*)(hb + ar0 * HH + akc0));
        float4 ra1 = __ldcg((const float4*)(hb + ar1 * HH + akc1));
        float4 rb  = *(const float4*)(wptr);

        int buf = 0;
        for (int kt = 0; kt < HH; kt += 16) {
            As[buf][akc0 + 0][ar0] = ra0.x; As[buf][akc0 + 1][ar0] = ra0.y;
            As[buf][akc0 + 2][ar0] = ra0.z; As[buf][akc0 + 3][ar0] = ra0.w;
            As[buf][akc1 + 0][ar1] = ra1.x; As[buf][akc1 + 1][ar1] = ra1.y;
            As[buf][akc1 + 2][ar1] = ra1.z; As[buf][akc1 + 3][ar1] = ra1.w;
            Bs[buf][bkc + 0][bcc]  = rb.x;  Bs[buf][bkc + 1][bcc]  = rb.y;
            Bs[buf][bkc + 2][bcc]  = rb.z;  Bs[buf][bkc + 3][bcc]  = rb.w;
            __syncthreads();

            if (kt + 16 < HH) {
                ra0 = __ldcg((const float4*)(hb + ar0 * HH + kt + 16 + akc0));
                ra1 = __ldcg((const float4*)(hb + ar1 * HH + kt + 16 + akc1));
                rb  = *(const float4*)(wptr + kt + 16);
            }

#pragma unroll
            for (int kk = 0; kk < 16; kk++) {
                float4 av = *(const float4*)(&As[buf][kk][r0]);
                float4 bv = *(const float4*)(&Bs[buf][kk][c0]);
                float aa[4] = {av.x, av.y, av.z, av.w};
                float bb[4] = {bv.x, bv.y, bv.z, bv.w};
#pragma unroll
                for (int i = 0; i < 4; i++)
#pragma unroll
                    for (int j = 0; j < 4; j++) acc[i][j] += aa[i] * bb[j];
            }
            buf ^= 1;
        }

        // exchange gates through smem (i/f/g/o for one h-idx live in 4 threads)
#pragma unroll
        for (int rr = 0; rr < 4; rr++)
#pragma unroll
            for (int c = 0; c < 4; c++)
                Gs[r0 + rr][c0 + c] = acc[rr][c];
        __syncthreads();

        // elementwise cell update: 512 (row, h) pairs, 4 per thread
#pragma unroll
        for (int q = 0; q < 4; q++) {
            int p    = q * 128 + tid;
            int row  = p >> 3;
            int hh   = p & 7;
            int hcol = h0 + hh;

            float zi = Gs[row][hh];
            float zf = Gs[row][8 + hh];
            float zg = Gs[row][16 + hh];
            float zo = Gs[row][24 + hh];

            float cold = g_cbuf[row * HH + hcol];
            float iv = sigmoidf_(zi + s_wci[hh] * cold);
            float fv = sigmoidf_(zf + s_wcf[hh] * cold);
            float gv = tanhf(zg);
            float cy = fv * cold + iv * gv;
            float ov = sigmoidf_(zo + s_wco[hh] * cy);
            float hy = ov * tanhf(cy);

            bool mm;
            if (mmode == 1)      mm = (m32[row * LL + t] != 0);
            else if (mmode == 2) mm = (mf[row * LL + t] != 0.0f);
            else                 mm = (m8[row * LL + t] != 0);

            float hold = __ldcg(hb + row * HH + hcol);
            float hnew = mm ? hy : hold;
            float cnew = mm ? cy : cold;

            g_cbuf[row * HH + hcol] = cnew;
            hn[row * HH + hcol]     = hnew;
            out[((size_t)row * LL + t) * HH + hcol] = hnew;
        }

        // grid-wide barrier (all 128 CTAs co-resident; fresh counter per step)
        __syncthreads();
        if (tid == 0) {
            __threadfence();
            atomicAdd(&g_bar[t], 1u);
            while (*(volatile unsigned*)&g_bar[t] < (unsigned)gridDim.x) {
                __nanosleep(64);
            }
            __threadfence();
        }
        __syncthreads();
    }
}

// ---------------- finalize: append h_T and c_T after outs ------------------
__global__ void finalize_kernel(float* __restrict__ out)
{
    int i = blockIdx.x * blockDim.x + threadIdx.x;
    if (i < BB * HH) {
        out[(size_t)BB * LL * HH + i]           = g_hbuf[0][i];  // final h (t=1023 wrote buf 0)
        out[(size_t)BB * LL * HH + BB * HH + i] = g_cbuf[i];
    }
}

// ---------------- launch ---------------------------------------------------
extern "C" void kernel_launch(void* const* d_in, const int* in_sizes, int n_in,
                              void* d_out, int out_size)
{
    (void)in_sizes; (void)n_in; (void)out_size;
    const float* X    = (const float*)d_in[0];
    const void*  mask = d_in[1];
    const float* Wih  = (const float*)d_in[2];
    const float* Whh  = (const float*)d_in[3];
    const float* bih  = (const float*)d_in[4];
    const float* bhh  = (const float*)d_in[5];
    const float* wci  = (const float*)d_in[6];
    const float* wcf  = (const float*)d_in[7];
    const float* wco  = (const float*)d_in[8];
    float* out = (float*)d_out;

    init_kernel<<<256, 256>>>(mask);

    dim3 g1(GG / 128, (BB * LL) / 128);   // (32, 512)
    gemm_x_kernel<<<g1, 256>>>(X, Wih, bih, bhh);

    lstm_kernel<<<NCTA, 128>>>(Whh,
                               (const unsigned char*)mask,
                               (const int*)mask,
                               (const float*)mask,
                               wci, wcf, wco, out);

    finalize_kernel<<<(BB * HH + 255) / 256, 256>>>(out);
}